// round 15
// baseline (speedup 1.0000x reference)
#include <cuda_runtime.h>
#include <cuda_bf16.h>
#include <cstdint>

// Problem constants
#define BATCH   4
#define T_TXT   2048
#define T_IMG   8
#define N_LAT   64
#define DIM     2048
#define DIM_VIS 1024
#define HEADS   8
#define DIM_HEAD 64
#define INNER   (HEADS * DIM_HEAD)      // 512
#define ROWS    (BATCH * T_TXT)         // 8192
#define KVROWS  (BATCH * T_IMG * N_LAT) // 2048
#define LN_EPS  1e-5f

// ---------------- scratch (static device, no allocs) ----------------
__device__ float g_xn[ROWS * DIM];
__device__ float g_q [ROWS * INNER];
__device__ float g_kv[KVROWS * 2 * INNER];
__device__ float g_ao[ROWS * INNER];
__device__ float g_wq_t [INNER * DIM];            // [n][k] tf32
__device__ float g_wout_t[DIM * INNER];           // [n][k] tf32
__device__ __nv_bfloat16 g_media_s[KVROWS * 3 * DIM_VIS];   // [row][hi|hi|lo]
__device__ __nv_bfloat16 g_wkv_s[2 * INNER * 3 * DIM_VIS];  // [n][hi|lo|hi]
__device__ int   g_qlist[BATCH][9][T_TXT];
__device__ int   g_qcount[BATCH][9];

__device__ __forceinline__ uint32_t f2tf32(float f) {
    uint32_t r;
    asm("cvt.rna.tf32.f32 %0, %1;" : "=r"(r) : "f"(f));
    return r;
}
__device__ __forceinline__ float rnd_tf32(float f) { return __uint_as_float(f2tf32(f)); }
__device__ __forceinline__ uint32_t smem_u32(const void* p) {
    uint32_t a;
    asm("{ .reg .u64 t; cvta.to.shared.u64 t, %1; cvt.u32.u64 %0, t; }" : "=r"(a) : "l"(p));
    return a;
}

#define CP_ASYNC16(dst, src) \
    asm volatile("cp.async.cg.shared.global [%0], [%1], 16;" :: "r"(dst), "l"(src))
#define CP_COMMIT() asm volatile("cp.async.commit_group;" ::: "memory")
#define CP_WAIT1()  asm volatile("cp.async.wait_group 1;" ::: "memory")
#define LDSM4(r0, r1, r2, r3, addr) \
    asm volatile("ldmatrix.sync.aligned.m8n8.x4.shared.b16 {%0,%1,%2,%3}, [%4];" \
        : "=r"(r0), "=r"(r1), "=r"(r2), "=r"(r3) : "r"(addr))

// ---------------- tf32 GEMM (unchanged from R14 winner) ----------------
#define KT 32
#define PR 36
#define STAGES 3

template<int MT>
__global__ __launch_bounds__(MT) void tf32gemm_lm(const float* __restrict__ A,
                                                  const float* __restrict__ Bt,
                                                  float* __restrict__ C,
                                                  int M, int N, int K) {
    constexpr int OP_A = MT * PR * 4;
    constexpr int OP_B = 128 * PR * 4;
    constexpr int STG  = OP_A + OP_B;
    extern __shared__ char smem[];
    const uint32_t sb = smem_u32(smem);
    const int tid = threadIdx.x;
    const int lane = tid & 31, warp = tid >> 5;
    const int tq = lane & 3, tg = lane >> 2;
    const int wm = (MT == 128) ? (warp >> 1) * 64 : 0;
    const int wn = (MT == 128) ? (warp & 1) * 64 : warp * 64;

    const int mblk = blockIdx.y * MT;
    const int nblk = blockIdx.x * 128;
    const float* Ab = A + (size_t)mblk * K;
    const float* Bb = Bt + (size_t)nblk * K;

    float acc[4][8][4];
    #pragma unroll
    for (int mf = 0; mf < 4; mf++)
        #pragma unroll
        for (int nf = 0; nf < 8; nf++)
            #pragma unroll
            for (int i = 0; i < 4; i++) acc[mf][nf][i] = 0.f;

    const int nK = K / KT;

    auto issue = [&](int s, int c) {
        const uint32_t sa = sb + s * STG;
        const uint32_t sB = sa + OP_A;
        const int k0 = c * KT;
        constexpr int ITERS = (MT * 8 + 1024) / MT;
        #pragma unroll
        for (int i = 0; i < ITERS; i++) {
            int id = tid + i * MT;
            if (id < MT * 8) {
                int row = id >> 3, c4 = id & 7;
                CP_ASYNC16(sa + row * (PR * 4) + c4 * 16,
                           Ab + (size_t)row * K + k0 + c4 * 4);
            } else {
                int idB = id - MT * 8;
                int row = idB >> 3, c4 = idB & 7;
                CP_ASYNC16(sB + row * (PR * 4) + c4 * 16,
                           Bb + (size_t)row * K + k0 + c4 * 4);
            }
        }
    };

    uint32_t a_off[4], b_off[4];
    #pragma unroll
    for (int mf = 0; mf < 4; mf++)
        a_off[mf] = ((wm + mf * 16 + (lane & 15)) * PR + ((lane >> 4) * 4)) * 4;
    #pragma unroll
    for (int p = 0; p < 4; p++)
        b_off[p] = OP_A +
            ((wn + p * 16 + ((lane >> 4) * 8) + (lane & 7)) * PR + (((lane >> 3) & 1) * 4)) * 4;

    issue(0, 0); CP_COMMIT();
    if (nK > 1) issue(1, 1);
    CP_COMMIT();

    int buf = 0;
    for (int c = 0; c < nK; c++) {
        CP_WAIT1();
        __syncthreads();
        if (c + 2 < nK) issue((c + 2) % STAGES, c + 2);
        CP_COMMIT();

        const uint32_t sbase = sb + buf * STG;

        #pragma unroll
        for (int ks = 0; ks < KT; ks += 8) {
            uint32_t af[4][4], bf[4][4];
            #pragma unroll
            for (int mf = 0; mf < 4; mf++)
                LDSM4(af[mf][0], af[mf][1], af[mf][2], af[mf][3],
                      sbase + a_off[mf] + ks * 4);
            #pragma unroll
            for (int p = 0; p < 4; p++)
                LDSM4(bf[p][0], bf[p][1], bf[p][2], bf[p][3],
                      sbase + b_off[p] + ks * 4);

            #pragma unroll
            for (int mf = 0; mf < 4; mf++)
                #pragma unroll
                for (int nf = 0; nf < 8; nf++) {
                    const uint32_t b0 = bf[nf >> 1][(nf & 1) * 2];
                    const uint32_t b1 = bf[nf >> 1][(nf & 1) * 2 + 1];
                    asm volatile(
                        "mma.sync.aligned.m16n8k8.row.col.f32.tf32.tf32.f32 "
                        "{%0,%1,%2,%3}, {%4,%5,%6,%7}, {%8,%9}, {%0,%1,%2,%3};"
                        : "+f"(acc[mf][nf][0]), "+f"(acc[mf][nf][1]),
                          "+f"(acc[mf][nf][2]), "+f"(acc[mf][nf][3])
                        : "r"(af[mf][0]), "r"(af[mf][1]), "r"(af[mf][2]), "r"(af[mf][3]),
                          "r"(b0), "r"(b1));
                }
        }
        __syncthreads();
        buf = (buf + 1) % STAGES;
    }

    #pragma unroll
    for (int mf = 0; mf < 4; mf++) {
        const int row0 = mblk + wm + mf * 16 + tg;
        #pragma unroll
        for (int nf = 0; nf < 8; nf++) {
            const int col = nblk + wn + nf * 8 + 2 * tq;
            *(float2*)(C + (size_t)row0 * N + col) =
                make_float2(acc[mf][nf][0], acc[mf][nf][1]);
            *(float2*)(C + (size_t)(row0 + 8) * N + col) =
                make_float2(acc[mf][nf][2], acc[mf][nf][3]);
        }
    }
}

#define SMEM128 (STAGES * (128 * PR * 4 + 128 * PR * 4))  // 110592

// ---------------- bf16 hi/lo 3-pass GEMM (kv probe; MT=64) ----------------
// C[M,N] = A'[M,K3] @ Bt'[N,K3]^T in bf16, fp32 accum.
// A' rows = [hi|hi|lo], B' rows = [hi|lo|hi] -> hi*hi + hi*lo + lo*hi.
#define KB 64                   // bf16 k per chunk (128B)
#define PRB 144                 // bytes per smem row (128 + 16 pad)
#define BOP_A (64 * PRB)        // 9216
#define BOP_B (128 * PRB)       // 18432
#define BSTG  (BOP_A + BOP_B)   // 27648
#define SMEMB (STAGES * BSTG)   // 82944

__global__ __launch_bounds__(64) void bf16gemm64(const __nv_bfloat16* __restrict__ A,
                                                 const __nv_bfloat16* __restrict__ Bt,
                                                 float* __restrict__ C,
                                                 int M, int N, int K3) {
    extern __shared__ char smem[];
    const uint32_t sb = smem_u32(smem);
    const int tid = threadIdx.x;
    const int lane = tid & 31, warp = tid >> 5;
    const int tq = lane & 3, tg = lane >> 2;
    const int wn = warp * 64;

    const int mblk = blockIdx.y * 64;
    const int nblk = blockIdx.x * 128;
    const __nv_bfloat16* Ab = A + (size_t)mblk * K3;
    const __nv_bfloat16* Bb = Bt + (size_t)nblk * K3;

    float acc[4][8][4];
    #pragma unroll
    for (int mf = 0; mf < 4; mf++)
        #pragma unroll
        for (int nf = 0; nf < 8; nf++)
            #pragma unroll
            for (int i = 0; i < 4; i++) acc[mf][nf][i] = 0.f;

    const int nK = K3 / KB;

    auto issue = [&](int s, int c) {
        const uint32_t sa = sb + s * BSTG;
        const uint32_t sB = sa + BOP_A;
        const int k0 = c * KB;
        #pragma unroll
        for (int i = 0; i < 24; i++) {          // (64+128)*8 chunks / 64 threads
            int id = tid + i * 64;
            if (id < 512) {                     // A: 64 rows x 8 chunks
                int row = id >> 3, c4 = id & 7;
                CP_ASYNC16(sa + row * PRB + c4 * 16,
                           Ab + (size_t)row * K3 + k0 + c4 * 8);
            } else {                            // B: 128 rows x 8 chunks
                int idB = id - 512;
                int row = idB >> 3, c4 = idB & 7;
                CP_ASYNC16(sB + row * PRB + c4 * 16,
                           Bb + (size_t)row * K3 + k0 + c4 * 8);
            }
        }
    };

    uint32_t a_off[4], b_off[4];
    #pragma unroll
    for (int mf = 0; mf < 4; mf++)
        a_off[mf] = (mf * 16 + (lane & 15)) * PRB + (lane >> 4) * 16;
    #pragma unroll
    for (int p = 0; p < 4; p++)
        b_off[p] = BOP_A + (wn + p * 16 + (lane & 15)) * PRB + (lane >> 4) * 16;

    issue(0, 0); CP_COMMIT();
    if (nK > 1) issue(1, 1);
    CP_COMMIT();

    int buf = 0;
    for (int c = 0; c < nK; c++) {
        CP_WAIT1();
        __syncthreads();
        if (c + 2 < nK) issue((c + 2) % STAGES, c + 2);
        CP_COMMIT();

        const uint32_t sbase = sb + buf * BSTG;

        #pragma unroll
        for (int ks = 0; ks < 4; ks++) {        // 4 x k16 steps
            uint32_t af[4][4], bp[4][4];
            #pragma unroll
            for (int mf = 0; mf < 4; mf++)
                LDSM4(af[mf][0], af[mf][1], af[mf][2], af[mf][3],
                      sbase + a_off[mf] + ks * 32);
            #pragma unroll
            for (int p = 0; p < 4; p++)
                LDSM4(bp[p][0], bp[p][1], bp[p][2], bp[p][3],
                      sbase + b_off[p] + ks * 32);

            #pragma unroll
            for (int mf = 0; mf < 4; mf++)
                #pragma unroll
                for (int nf = 0; nf < 8; nf++) {
                    const uint32_t b0 = bp[nf >> 1][nf & 1];
                    const uint32_t b1 = bp[nf >> 1][(nf & 1) + 2];
                    asm volatile(
                        "mma.sync.aligned.m16n8k16.row.col.f32.bf16.bf16.f32 "
                        "{%0,%1,%2,%3}, {%4,%5,%6,%7}, {%8,%9}, {%0,%1,%2,%3};"
                        : "+f"(acc[mf][nf][0]), "+f"(acc[mf][nf][1]),
                          "+f"(acc[mf][nf][2]), "+f"(acc[mf][nf][3])
                        : "r"(af[mf][0]), "r"(af[mf][1]), "r"(af[mf][2]), "r"(af[mf][3]),
                          "r"(b0), "r"(b1));
                }
        }
        __syncthreads();
        buf = (buf + 1) % STAGES;
    }

    #pragma unroll
    for (int mf = 0; mf < 4; mf++) {
        const int row0 = mblk + mf * 16 + tg;
        #pragma unroll
        for (int nf = 0; nf < 8; nf++) {
            const int col = nblk + wn + nf * 8 + 2 * tq;
            *(float2*)(C + (size_t)row0 * N + col) =
                make_float2(acc[mf][nf][0], acc[mf][nf][1]);
            *(float2*)(C + (size_t)(row0 + 8) * N + col) =
                make_float2(acc[mf][nf][2], acc[mf][nf][3]);
        }
    }
}

// ---------------- split producers for the bf16 path ----------------
// A-side: in [rows][K] fp32 -> out [rows][3K] bf16 = [hi|hi|lo]
__global__ __launch_bounds__(256) void cvt_split_A(const float* __restrict__ in,
                                                   __nv_bfloat16* __restrict__ out, int K) {
    int i = blockIdx.x * 256 + threadIdx.x;
    int row = i / K, k = i - row * K;
    float x = in[i];
    __nv_bfloat16 hi = __float2bfloat16(x);
    __nv_bfloat16 lo = __float2bfloat16(x - __bfloat162float(hi));
    __nv_bfloat16* o = out + (size_t)row * 3 * K;
    o[k] = hi; o[K + k] = hi; o[2 * K + k] = lo;
}

// B-side: in [K][N] fp32 -> out [N][3K] bf16 = [hi|lo|hi]
__global__ __launch_bounds__(256) void wtrans_split(const float* __restrict__ in,
                                                    __nv_bfloat16* __restrict__ out,
                                                    int K, int N) {
    __shared__ float t[32][33];
    const int k0 = blockIdx.y * 32, n0 = blockIdx.x * 32;
    const int tx = threadIdx.x & 31, ty = threadIdx.x >> 5;
    #pragma unroll
    for (int i = ty; i < 32; i += 8)
        t[i][tx] = in[(size_t)(k0 + i) * N + n0 + tx];
    __syncthreads();
    #pragma unroll
    for (int i = ty; i < 32; i += 8) {
        const int n = n0 + i, k = k0 + tx;
        float x = t[tx][i];
        __nv_bfloat16 hi = __float2bfloat16(x);
        __nv_bfloat16 lo = __float2bfloat16(x - __bfloat162float(hi));
        __nv_bfloat16* o = out + (size_t)n * 3 * K;
        o[k] = hi; o[K + k] = lo; o[2 * K + k] = hi;
    }
}

// ---------------- weight transpose [K][N] -> [N][K] + tf32 round ----------------
__global__ __launch_bounds__(256) void wtrans_kernel(const float* __restrict__ in,
                                                     float* __restrict__ out,
                                                     int K, int N) {
    __shared__ float t[32][33];
    const int k0 = blockIdx.y * 32, n0 = blockIdx.x * 32;
    const int tx = threadIdx.x & 31, ty = threadIdx.x >> 5;
    #pragma unroll
    for (int i = ty; i < 32; i += 8)
        t[i][tx] = in[(size_t)(k0 + i) * N + n0 + tx];
    __syncthreads();
    #pragma unroll
    for (int i = ty; i < 32; i += 8)
        out[(size_t)(n0 + i) * K + k0 + tx] = rnd_tf32(t[tx][i]);
}

// ---------------- LayerNorm (single pass, tf32-rounded output) ----------------
__global__ __launch_bounds__(256) void ln_kernel(const float* __restrict__ x,
                                                 const float* __restrict__ gamma,
                                                 const float* __restrict__ beta) {
    const int row = blockIdx.x;
    const float4* xr = (const float4*)(x + (size_t)row * DIM);
    float4* out = (float4*)(g_xn + (size_t)row * DIM);
    const int tid = threadIdx.x;

    __shared__ float reds[256], redq[256];
    float s = 0.f, sq = 0.f;
    #pragma unroll
    for (int c = tid; c < DIM / 4; c += 256) {
        float4 v = xr[c];
        s  += v.x + v.y + v.z + v.w;
        sq += v.x * v.x + v.y * v.y + v.z * v.z + v.w * v.w;
    }
    reds[tid] = s; redq[tid] = sq; __syncthreads();
    for (int o = 128; o > 0; o >>= 1) {
        if (tid < o) { reds[tid] += reds[tid + o]; redq[tid] += redq[tid + o]; }
        __syncthreads();
    }
    const float mu = reds[0] * (1.0f / DIM);
    const float var = redq[0] * (1.0f / DIM) - mu * mu;
    const float rstd = rsqrtf(var + LN_EPS);

    const float4* g4 = (const float4*)gamma;
    const float4* b4 = (const float4*)beta;
    #pragma unroll
    for (int c = tid; c < DIM / 4; c += 256) {
        float4 v = xr[c], g = g4[c], bb = b4[c], o4;
        o4.x = rnd_tf32((v.x - mu) * rstd * g.x + bb.x);
        o4.y = rnd_tf32((v.y - mu) * rstd * g.y + bb.y);
        o4.z = rnd_tf32((v.z - mu) * rstd * g.z + bb.z);
        o4.w = rnd_tf32((v.w - mu) * rstd * g.w + bb.w);
        out[c] = o4;
    }
}

// ---------------- parallel build of per-(b,tt) query lists ----------------
__global__ __launch_bounds__(256) void build_lists2(const int* __restrict__ locs) {
    const int b = blockIdx.x;
    const int tid = threadIdx.x;
    __shared__ int ssum[256];
    __shared__ int cnt[9];

    const int base = tid * 8;
    int v[8];
    int s = 0;
    #pragma unroll
    for (int j = 0; j < 8; j++) { v[j] = locs[b * T_TXT + base + j]; s += v[j]; }
    ssum[tid] = s;
    if (tid < 9) cnt[tid] = 0;
    __syncthreads();
    for (int off = 1; off < 256; off <<= 1) {
        int t = (tid >= off) ? ssum[tid - off] : 0;
        __syncthreads();
        ssum[tid] += t;
        __syncthreads();
    }
    int run = ssum[tid] - s;
    #pragma unroll
    for (int j = 0; j < 8; j++) {
        run += v[j];
        int p = atomicAdd(&cnt[run], 1);
        g_qlist[b][run][p] = base + j;
    }
    __syncthreads();
    if (tid < 9) g_qcount[b][tid] = cnt[tid];
}

// ---------------- masked chunk attention (query-chunked grid) ----------------
#define QCHUNK 128
#define NCHUNK (T_TXT / QCHUNK)   // 16

__global__ __launch_bounds__(256) void attn_kernel() {
    const int blk = blockIdx.x;                 // b*72 + h*9 + tt
    const int b = blk / 72;
    const int h = (blk / 9) % 8;
    const int tt = blk % 9;
    const int start = blockIdx.y * QCHUNK;
    const int cnt = g_qcount[b][tt];
    if (start >= cnt) return;
    const int qend = min(cnt, start + QCHUNK);

    const int lane = threadIdx.x & 31;
    const int warp = threadIdx.x >> 5;

    if (tt == 0) {
        for (int qi = start + warp; qi < qend; qi += 8) {
            int i = g_qlist[b][0][qi];
            float* dst = g_ao + (size_t)(b * T_TXT + i) * INNER + h * DIM_HEAD;
            dst[lane] = 0.f; dst[lane + 32] = 0.f;
        }
        return;
    }

    __shared__ float ksh[64][65];
    __shared__ float vsh[64][65];
    const int base = b * 512 + (tt - 1) * 64;
    for (int idx = threadIdx.x; idx < 4096; idx += 256) {
        int r = idx >> 6, c = idx & 63;
        const float* kvr = g_kv + (size_t)(base + r) * (2 * INNER);
        ksh[r][c] = kvr[h * DIM_HEAD + c];
        vsh[r][c] = kvr[INNER + h * DIM_HEAD + c];
    }
    __syncthreads();

    const float scale = 0.125f;
    for (int qi = start + warp; qi < qend; qi += 8) {
        const int i = g_qlist[b][tt][qi];
        const float* qr = g_q + (size_t)(b * T_TXT + i) * INNER + h * DIM_HEAD;
        const float q0 = qr[lane] * scale;
        const float q1 = qr[lane + 32] * scale;

        float s0 = 0.f, s1 = 0.f;
        #pragma unroll
        for (int d = 0; d < 32; d++) {
            float qd = __shfl_sync(0xffffffffu, q0, d);
            s0 += qd * ksh[lane][d];
            s1 += qd * ksh[lane + 32][d];
        }
        #pragma unroll
        for (int d = 0; d < 32; d++) {
            float qd = __shfl_sync(0xffffffffu, q1, d);
            s0 += qd * ksh[lane][d + 32];
            s1 += qd * ksh[lane + 32][d + 32];
        }
        float m = fmaxf(s0, s1);
        #pragma unroll
        for (int o = 16; o > 0; o >>= 1) m = fmaxf(m, __shfl_xor_sync(0xffffffffu, m, o));
        float p0 = __expf(s0 - m), p1 = __expf(s1 - m);
        float sum = p0 + p1;
        #pragma unroll
        for (int o = 16; o > 0; o >>= 1) sum += __shfl_xor_sync(0xffffffffu, sum, o);
        const float inv = 1.f / sum;
        p0 *= inv; p1 *= inv;

        float o0 = 0.f, o1 = 0.f;
        #pragma unroll
        for (int j = 0; j < 32; j++) {
            float pa = __shfl_sync(0xffffffffu, p0, j);
            float pb = __shfl_sync(0xffffffffu, p1, j);
            o0 += pa * vsh[j][lane]      + pb * vsh[j + 32][lane];
            o1 += pa * vsh[j][lane + 32] + pb * vsh[j + 32][lane + 32];
        }
        float* dst = g_ao + (size_t)(b * T_TXT + i) * INNER + h * DIM_HEAD;
        dst[lane]      = rnd_tf32(o0);
        dst[lane + 32] = rnd_tf32(o1);
    }
}

// ---------------- launch (stream DAG; bf16 kv-GEMM probe in ncu slot) ----------------
extern "C" void kernel_launch(void* const* d_in, const int* in_sizes, int n_in,
                              void* d_out, int out_size) {
    const float* x     = (const float*)d_in[0];
    const float* media = (const float*)d_in[1];
    const int*   locs  = (const int*)d_in[2];
    const float* gamma = (const float*)d_in[3];
    const float* beta  = (const float*)d_in[4];
    const float* Wq    = (const float*)d_in[5];
    const float* Wkv   = (const float*)d_in[6];
    const float* Wout  = (const float*)d_in[7];
    float*       out   = (float*)d_out;

    float *p_xn, *p_q, *p_kv, *p_ao, *p_wq, *p_wout;
    __nv_bfloat16 *p_media_s, *p_wkv_s;
    cudaGetSymbolAddress((void**)&p_xn, g_xn);
    cudaGetSymbolAddress((void**)&p_q,  g_q);
    cudaGetSymbolAddress((void**)&p_kv, g_kv);
    cudaGetSymbolAddress((void**)&p_ao, g_ao);
    cudaGetSymbolAddress((void**)&p_wq, g_wq_t);
    cudaGetSymbolAddress((void**)&p_wout, g_wout_t);
    cudaGetSymbolAddress((void**)&p_media_s, g_media_s);
    cudaGetSymbolAddress((void**)&p_wkv_s, g_wkv_s);

    cudaFuncSetAttribute(tf32gemm_lm<128>, cudaFuncAttributeMaxDynamicSharedMemorySize, SMEM128);
    cudaFuncSetAttribute(bf16gemm64, cudaFuncAttributeMaxDynamicSharedMemorySize, SMEMB);

    static cudaStream_t s1 = nullptr, s2 = nullptr;
    static cudaEvent_t eFork = nullptr, eKv = nullptr, eBl = nullptr, eWout = nullptr, eWq = nullptr;
    if (s1 == nullptr) {
        cudaStreamCreateWithFlags(&s1, cudaStreamNonBlocking);
        cudaStreamCreateWithFlags(&s2, cudaStreamNonBlocking);
        cudaEventCreateWithFlags(&eFork, cudaEventDisableTiming);
        cudaEventCreateWithFlags(&eKv,   cudaEventDisableTiming);
        cudaEventCreateWithFlags(&eBl,   cudaEventDisableTiming);
        cudaEventCreateWithFlags(&eWout, cudaEventDisableTiming);
        cudaEventCreateWithFlags(&eWq,   cudaEventDisableTiming);
    }

    cudaEventRecord(eFork, 0);
    cudaStreamWaitEvent(s1, eFork, 0);
    cudaStreamWaitEvent(s2, eFork, 0);

    // main: ln -> (wait Wq) -> q-GEMM -> attn -> (wait Wout) -> out-GEMM
    ln_kernel<<<ROWS, 256>>>(x, gamma, beta);                                   // 1

    // s1: Wkv split + media split -> bf16 kv-GEMM (hidden probe)
    wtrans_split<<<dim3(2 * INNER / 32, DIM_VIS / 32), 256, 0, s1>>>(Wkv, p_wkv_s, DIM_VIS, 2 * INNER); // 2
    cvt_split_A<<<(KVROWS * DIM_VIS) / 256, 256, 0, s1>>>(media, p_media_s, DIM_VIS);                   // 3
    bf16gemm64<<<dim3((2 * INNER) / 128, KVROWS / 64), 64, SMEMB, s1>>>(        // 4  <-- profiled slot
        p_media_s, p_wkv_s, p_kv, KVROWS, 2 * INNER, 3 * DIM_VIS);
    cudaEventRecord(eKv, s1);

    // s2: Wq-trans -> build_lists -> Wout-trans
    wtrans_kernel<<<dim3(INNER / 32, DIM / 32), 256, 0, s2>>>(Wq, p_wq, DIM, INNER);  // 5
    cudaEventRecord(eWq, s2);
    build_lists2<<<BATCH, 256, 0, s2>>>(locs);                                        // 6
    cudaEventRecord(eBl, s2);
    wtrans_kernel<<<dim3(DIM / 32, INNER / 32), 256, 0, s2>>>(Wout, p_wout, INNER, DIM); // 7
    cudaEventRecord(eWout, s2);

    // main continues
    cudaStreamWaitEvent(0, eWq, 0);
    tf32gemm_lm<128><<<dim3(INNER / 128, ROWS / 128), 128, SMEM128>>>(          // 8
        p_xn, p_wq, p_q, ROWS, INNER, DIM);

    cudaStreamWaitEvent(0, eKv, 0);
    cudaStreamWaitEvent(0, eBl, 0);
    attn_kernel<<<dim3(BATCH * HEADS * 9, NCHUNK), 256>>>();                    // 9

    cudaStreamWaitEvent(0, eWout, 0);
    tf32gemm_lm<128><<<dim3(DIM / 128, ROWS / 128), 128, SMEM128>>>(            // 10
        p_ao, p_wout, out, ROWS, DIM, INNER);
}

// round 17
// speedup vs baseline: 1.0786x; 1.0786x over previous
#include <cuda_runtime.h>
#include <cuda_bf16.h>
#include <cstdint>

// Problem constants
#define BATCH   4
#define T_TXT   2048
#define T_IMG   8
#define N_LAT   64
#define DIM     2048
#define DIM_VIS 1024
#define HEADS   8
#define DIM_HEAD 64
#define INNER   (HEADS * DIM_HEAD)      // 512
#define ROWS    (BATCH * T_TXT)         // 8192
#define KVROWS  (BATCH * T_IMG * N_LAT) // 2048
#define LN_EPS  1e-5f

// ---------------- scratch (static device, no allocs) ----------------
__device__ float g_xn[ROWS * DIM];
__device__ float g_q [ROWS * INNER];
__device__ float g_kv[KVROWS * 2 * INNER];
__device__ float g_ao[ROWS * INNER];
__device__ float g_wq_t [INNER * DIM];        // [n][k] tf32
__device__ float g_wkv_t[2 * INNER * DIM_VIS];// [n][k] tf32
__device__ float g_wout_t[DIM * INNER];       // [n][k] tf32
__device__ float g_media_t[KVROWS * DIM_VIS];
__device__ int   g_qlist[BATCH][9][T_TXT];
__device__ int   g_qcount[BATCH][9];

__device__ __forceinline__ uint32_t f2tf32(float f) {
    uint32_t r;
    asm("cvt.rna.tf32.f32 %0, %1;" : "=r"(r) : "f"(f));
    return r;
}
__device__ __forceinline__ float rnd_tf32(float f) { return __uint_as_float(f2tf32(f)); }
__device__ __forceinline__ uint32_t smem_u32(const void* p) {
    uint32_t a;
    asm("{ .reg .u64 t; cvta.to.shared.u64 t, %1; cvt.u32.u64 %0, t; }" : "=r"(a) : "l"(p));
    return a;
}

#define CP_ASYNC16(dst, src) \
    asm volatile("cp.async.cg.shared.global [%0], [%1], 16;" :: "r"(dst), "l"(src))
#define CP_COMMIT() asm volatile("cp.async.commit_group;" ::: "memory")
#define CP_WAIT1()  asm volatile("cp.async.wait_group 1;" ::: "memory")
#define LDSM4(r0, r1, r2, r3, addr) \
    asm volatile("ldmatrix.sync.aligned.m8n8.x4.shared.b16 {%0,%1,%2,%3}, [%4];" \
        : "=r"(r0), "=r"(r1), "=r"(r2), "=r"(r3) : "r"(addr))

// ---------------- cp.async + ldmatrix pipelined TF32 GEMM ----------------
#define KT 32
#define PR 36
#define STAGES 3

template<int MT>
__global__ __launch_bounds__(MT) void tf32gemm_lm(const float* __restrict__ A,
                                                  const float* __restrict__ Bt,
                                                  float* __restrict__ C,
                                                  int M, int N, int K) {
    constexpr int OP_A = MT * PR * 4;
    constexpr int OP_B = 128 * PR * 4;
    constexpr int STG  = OP_A + OP_B;
    extern __shared__ char smem[];
    const uint32_t sb = smem_u32(smem);
    const int tid = threadIdx.x;
    const int lane = tid & 31, warp = tid >> 5;
    const int tq = lane & 3, tg = lane >> 2;
    const int wm = (MT == 128) ? (warp >> 1) * 64 : 0;
    const int wn = (MT == 128) ? (warp & 1) * 64 : warp * 64;

    const int mblk = blockIdx.y * MT;
    const int nblk = blockIdx.x * 128;
    const float* Ab = A + (size_t)mblk * K;
    const float* Bb = Bt + (size_t)nblk * K;

    float acc[4][8][4];
    #pragma unroll
    for (int mf = 0; mf < 4; mf++)
        #pragma unroll
        for (int nf = 0; nf < 8; nf++)
            #pragma unroll
            for (int i = 0; i < 4; i++) acc[mf][nf][i] = 0.f;

    const int nK = K / KT;

    auto issue = [&](int s, int c) {
        const uint32_t sa = sb + s * STG;
        const uint32_t sB = sa + OP_A;
        const int k0 = c * KT;
        constexpr int ITERS = (MT * 8 + 1024) / MT;
        #pragma unroll
        for (int i = 0; i < ITERS; i++) {
            int id = tid + i * MT;
            if (id < MT * 8) {
                int row = id >> 3, c4 = id & 7;
                CP_ASYNC16(sa + row * (PR * 4) + c4 * 16,
                           Ab + (size_t)row * K + k0 + c4 * 4);
            } else {
                int idB = id - MT * 8;
                int row = idB >> 3, c4 = idB & 7;
                CP_ASYNC16(sB + row * (PR * 4) + c4 * 16,
                           Bb + (size_t)row * K + k0 + c4 * 4);
            }
        }
    };

    uint32_t a_off[4], b_off[4];
    #pragma unroll
    for (int mf = 0; mf < 4; mf++)
        a_off[mf] = ((wm + mf * 16 + (lane & 15)) * PR + ((lane >> 4) * 4)) * 4;
    #pragma unroll
    for (int p = 0; p < 4; p++)
        b_off[p] = OP_A +
            ((wn + p * 16 + ((lane >> 4) * 8) + (lane & 7)) * PR + (((lane >> 3) & 1) * 4)) * 4;

    issue(0, 0); CP_COMMIT();
    if (nK > 1) issue(1, 1);
    CP_COMMIT();

    int buf = 0;
    for (int c = 0; c < nK; c++) {
        CP_WAIT1();
        __syncthreads();
        if (c + 2 < nK) issue((c + 2) % STAGES, c + 2);
        CP_COMMIT();

        const uint32_t sbase = sb + buf * STG;

        #pragma unroll
        for (int ks = 0; ks < KT; ks += 8) {
            uint32_t af[4][4], bf[4][4];
            #pragma unroll
            for (int mf = 0; mf < 4; mf++)
                LDSM4(af[mf][0], af[mf][1], af[mf][2], af[mf][3],
                      sbase + a_off[mf] + ks * 4);
            #pragma unroll
            for (int p = 0; p < 4; p++)
                LDSM4(bf[p][0], bf[p][1], bf[p][2], bf[p][3],
                      sbase + b_off[p] + ks * 4);

            #pragma unroll
            for (int mf = 0; mf < 4; mf++)
                #pragma unroll
                for (int nf = 0; nf < 8; nf++) {
                    const uint32_t b0 = bf[nf >> 1][(nf & 1) * 2];
                    const uint32_t b1 = bf[nf >> 1][(nf & 1) * 2 + 1];
                    asm volatile(
                        "mma.sync.aligned.m16n8k8.row.col.f32.tf32.tf32.f32 "
                        "{%0,%1,%2,%3}, {%4,%5,%6,%7}, {%8,%9}, {%0,%1,%2,%3};"
                        : "+f"(acc[mf][nf][0]), "+f"(acc[mf][nf][1]),
                          "+f"(acc[mf][nf][2]), "+f"(acc[mf][nf][3])
                        : "r"(af[mf][0]), "r"(af[mf][1]), "r"(af[mf][2]), "r"(af[mf][3]),
                          "r"(b0), "r"(b1));
                }
        }
        __syncthreads();
        buf = (buf + 1) % STAGES;
    }

    #pragma unroll
    for (int mf = 0; mf < 4; mf++) {
        const int row0 = mblk + wm + mf * 16 + tg;
        #pragma unroll
        for (int nf = 0; nf < 8; nf++) {
            const int col = nblk + wn + nf * 8 + 2 * tq;
            *(float2*)(C + (size_t)row0 * N + col) =
                make_float2(acc[mf][nf][0], acc[mf][nf][1]);
            *(float2*)(C + (size_t)(row0 + 8) * N + col) =
                make_float2(acc[mf][nf][2], acc[mf][nf][3]);
        }
    }
}

#define SMEM128 (STAGES * (128 * PR * 4 + 128 * PR * 4))  // 110592
#define SMEM64  (STAGES * (64 * PR * 4 + 128 * PR * 4))   // 82944

// ---------------- weight transpose [K][N] -> [N][K] + tf32 round ----------------
__global__ __launch_bounds__(256) void wtrans_kernel(const float* __restrict__ in,
                                                     float* __restrict__ out,
                                                     int K, int N) {
    __shared__ float t[32][33];
    const int k0 = blockIdx.y * 32, n0 = blockIdx.x * 32;
    const int tx = threadIdx.x & 31, ty = threadIdx.x >> 5;
    #pragma unroll
    for (int i = ty; i < 32; i += 8)
        t[i][tx] = in[(size_t)(k0 + i) * N + n0 + tx];
    __syncthreads();
    #pragma unroll
    for (int i = ty; i < 32; i += 8)
        out[(size_t)(n0 + i) * K + k0 + tx] = rnd_tf32(t[tx][i]);
}

// ---------------- tf32 pre-round (rna) for media ----------------
__global__ __launch_bounds__(256) void cvt_tf32_kernel(const float* __restrict__ in,
                                                       float* __restrict__ out, int n4) {
    int i = blockIdx.x * 256 + threadIdx.x;
    if (i < n4) {
        float4 v = ((const float4*)in)[i];
        v.x = rnd_tf32(v.x); v.y = rnd_tf32(v.y); v.z = rnd_tf32(v.z); v.w = rnd_tf32(v.w);
        ((float4*)out)[i] = v;
    }
}

// ---------------- LayerNorm (single pass, tf32-rounded output) ----------------
__global__ __launch_bounds__(256) void ln_kernel(const float* __restrict__ x,
                                                 const float* __restrict__ gamma,
                                                 const float* __restrict__ beta) {
    const int row = blockIdx.x;
    const float4* xr = (const float4*)(x + (size_t)row * DIM);
    float4* out = (float4*)(g_xn + (size_t)row * DIM);
    const int tid = threadIdx.x;

    __shared__ float reds[256], redq[256];
    float s = 0.f, sq = 0.f;
    #pragma unroll
    for (int c = tid; c < DIM / 4; c += 256) {
        float4 v = xr[c];
        s  += v.x + v.y + v.z + v.w;
        sq += v.x * v.x + v.y * v.y + v.z * v.z + v.w * v.w;
    }
    reds[tid] = s; redq[tid] = sq; __syncthreads();
    for (int o = 128; o > 0; o >>= 1) {
        if (tid < o) { reds[tid] += reds[tid + o]; redq[tid] += redq[tid + o]; }
        __syncthreads();
    }
    const float mu = reds[0] * (1.0f / DIM);
    const float var = redq[0] * (1.0f / DIM) - mu * mu;
    const float rstd = rsqrtf(var + LN_EPS);

    const float4* g4 = (const float4*)gamma;
    const float4* b4 = (const float4*)beta;
    #pragma unroll
    for (int c = tid; c < DIM / 4; c += 256) {
        float4 v = xr[c], g = g4[c], bb = b4[c], o4;
        o4.x = rnd_tf32((v.x - mu) * rstd * g.x + bb.x);
        o4.y = rnd_tf32((v.y - mu) * rstd * g.y + bb.y);
        o4.z = rnd_tf32((v.z - mu) * rstd * g.z + bb.z);
        o4.w = rnd_tf32((v.w - mu) * rstd * g.w + bb.w);
        out[c] = o4;
    }
}

// ---------------- parallel build of per-(b,tt) query lists ----------------
__global__ __launch_bounds__(256) void build_lists2(const int* __restrict__ locs) {
    const int b = blockIdx.x;
    const int tid = threadIdx.x;
    __shared__ int ssum[256];
    __shared__ int cnt[9];

    const int base = tid * 8;
    int v[8];
    int s = 0;
    #pragma unroll
    for (int j = 0; j < 8; j++) { v[j] = locs[b * T_TXT + base + j]; s += v[j]; }
    ssum[tid] = s;
    if (tid < 9) cnt[tid] = 0;
    __syncthreads();
    for (int off = 1; off < 256; off <<= 1) {
        int t = (tid >= off) ? ssum[tid - off] : 0;
        __syncthreads();
        ssum[tid] += t;
        __syncthreads();
    }
    int run = ssum[tid] - s;
    #pragma unroll
    for (int j = 0; j < 8; j++) {
        run += v[j];
        int p = atomicAdd(&cnt[run], 1);
        g_qlist[b][run][p] = base + j;
    }
    __syncthreads();
    if (tid < 9) g_qcount[b][tid] = cnt[tid];
}

// ---------------- masked chunk attention (query-chunked grid) ----------------
#define QCHUNK 128
#define NCHUNK (T_TXT / QCHUNK)   // 16

__global__ __launch_bounds__(256) void attn_kernel() {
    const int blk = blockIdx.x;                 // b*72 + h*9 + tt
    const int b = blk / 72;
    const int h = (blk / 9) % 8;
    const int tt = blk % 9;
    const int start = blockIdx.y * QCHUNK;
    const int cnt = g_qcount[b][tt];
    if (start >= cnt) return;
    const int qend = min(cnt, start + QCHUNK);

    const int lane = threadIdx.x & 31;
    const int warp = threadIdx.x >> 5;

    if (tt == 0) {
        for (int qi = start + warp; qi < qend; qi += 8) {
            int i = g_qlist[b][0][qi];
            float* dst = g_ao + (size_t)(b * T_TXT + i) * INNER + h * DIM_HEAD;
            dst[lane] = 0.f; dst[lane + 32] = 0.f;
        }
        return;
    }

    __shared__ float ksh[64][65];
    __shared__ float vsh[64][65];
    const int base = b * 512 + (tt - 1) * 64;
    for (int idx = threadIdx.x; idx < 4096; idx += 256) {
        int r = idx >> 6, c = idx & 63;
        const float* kvr = g_kv + (size_t)(base + r) * (2 * INNER);
        ksh[r][c] = kvr[h * DIM_HEAD + c];
        vsh[r][c] = kvr[INNER + h * DIM_HEAD + c];
    }
    __syncthreads();

    const float scale = 0.125f;
    for (int qi = start + warp; qi < qend; qi += 8) {
        const int i = g_qlist[b][tt][qi];
        const float* qr = g_q + (size_t)(b * T_TXT + i) * INNER + h * DIM_HEAD;
        const float q0 = qr[lane] * scale;
        const float q1 = qr[lane + 32] * scale;

        float s0 = 0.f, s1 = 0.f;
        #pragma unroll
        for (int d = 0; d < 32; d++) {
            float qd = __shfl_sync(0xffffffffu, q0, d);
            s0 += qd * ksh[lane][d];
            s1 += qd * ksh[lane + 32][d];
        }
        #pragma unroll
        for (int d = 0; d < 32; d++) {
            float qd = __shfl_sync(0xffffffffu, q1, d);
            s0 += qd * ksh[lane][d + 32];
            s1 += qd * ksh[lane + 32][d + 32];
        }
        float m = fmaxf(s0, s1);
        #pragma unroll
        for (int o = 16; o > 0; o >>= 1) m = fmaxf(m, __shfl_xor_sync(0xffffffffu, m, o));
        float p0 = __expf(s0 - m), p1 = __expf(s1 - m);
        float sum = p0 + p1;
        #pragma unroll
        for (int o = 16; o > 0; o >>= 1) sum += __shfl_xor_sync(0xffffffffu, sum, o);
        const float inv = 1.f / sum;
        p0 *= inv; p1 *= inv;

        float o0 = 0.f, o1 = 0.f;
        #pragma unroll
        for (int j = 0; j < 32; j++) {
            float pa = __shfl_sync(0xffffffffu, p0, j);
            float pb = __shfl_sync(0xffffffffu, p1, j);
            o0 += pa * vsh[j][lane]      + pb * vsh[j + 32][lane];
            o1 += pa * vsh[j][lane + 32] + pb * vsh[j + 32][lane + 32];
        }
        float* dst = g_ao + (size_t)(b * T_TXT + i) * INNER + h * DIM_HEAD;
        dst[lane]      = rnd_tf32(o0);
        dst[lane + 32] = rnd_tf32(o1);
    }
}

// ---------------- launch: R14 topology + Wq-trans moved off critical path ----------------
extern "C" void kernel_launch(void* const* d_in, const int* in_sizes, int n_in,
                              void* d_out, int out_size) {
    const float* x     = (const float*)d_in[0];
    const float* media = (const float*)d_in[1];
    const int*   locs  = (const int*)d_in[2];
    const float* gamma = (const float*)d_in[3];
    const float* beta  = (const float*)d_in[4];
    const float* Wq    = (const float*)d_in[5];
    const float* Wkv   = (const float*)d_in[6];
    const float* Wout  = (const float*)d_in[7];
    float*       out   = (float*)d_out;

    float *p_xn, *p_q, *p_kv, *p_ao, *p_wq, *p_wkv, *p_wout, *p_media;
    cudaGetSymbolAddress((void**)&p_xn, g_xn);
    cudaGetSymbolAddress((void**)&p_q,  g_q);
    cudaGetSymbolAddress((void**)&p_kv, g_kv);
    cudaGetSymbolAddress((void**)&p_ao, g_ao);
    cudaGetSymbolAddress((void**)&p_wq, g_wq_t);
    cudaGetSymbolAddress((void**)&p_wkv, g_wkv_t);
    cudaGetSymbolAddress((void**)&p_wout, g_wout_t);
    cudaGetSymbolAddress((void**)&p_media, g_media_t);

    cudaFuncSetAttribute(tf32gemm_lm<128>, cudaFuncAttributeMaxDynamicSharedMemorySize, SMEM128);
    cudaFuncSetAttribute(tf32gemm_lm<64>,  cudaFuncAttributeMaxDynamicSharedMemorySize, SMEM64);

    static cudaStream_t s1 = nullptr, s2 = nullptr;
    static cudaEvent_t eFork = nullptr, eKv = nullptr, eBl = nullptr, eWout = nullptr, eWq = nullptr;
    if (s1 == nullptr) {
        cudaStreamCreateWithFlags(&s1, cudaStreamNonBlocking);
        cudaStreamCreateWithFlags(&s2, cudaStreamNonBlocking);
        cudaEventCreateWithFlags(&eFork, cudaEventDisableTiming);
        cudaEventCreateWithFlags(&eKv,   cudaEventDisableTiming);
        cudaEventCreateWithFlags(&eBl,   cudaEventDisableTiming);
        cudaEventCreateWithFlags(&eWout, cudaEventDisableTiming);
        cudaEventCreateWithFlags(&eWq,   cudaEventDisableTiming);
    }

    cudaEventRecord(eFork, 0);
    cudaStreamWaitEvent(s1, eFork, 0);
    cudaStreamWaitEvent(s2, eFork, 0);

    // main: ln (Wq-trans now on s2)
    ln_kernel<<<ROWS, 256>>>(x, gamma, beta);                                   // 1

    // s1: Wkv-trans -> media-cvt -> kv-GEMM (tf32, hidden)
    wtrans_kernel<<<dim3(2 * INNER / 32, DIM_VIS / 32), 256, 0, s1>>>(Wkv, p_wkv, DIM_VIS, 2 * INNER); // 2
    cvt_tf32_kernel<<<(KVROWS * DIM_VIS / 4) / 256, 256, 0, s1>>>(media, p_media, KVROWS * DIM_VIS / 4); // 3
    tf32gemm_lm<64><<<dim3((2 * INNER) / 128, KVROWS / 64), 64, SMEM64, s1>>>(  // 4 <-- profiled slot
        p_media, p_wkv, p_kv, KVROWS, 2 * INNER, DIM_VIS);
    cudaEventRecord(eKv, s1);

    // s2: Wq-trans -> build_lists -> Wout-trans
    wtrans_kernel<<<dim3(INNER / 32, DIM / 32), 256, 0, s2>>>(Wq, p_wq, DIM, INNER);   // 5
    cudaEventRecord(eWq, s2);
    build_lists2<<<BATCH, 256, 0, s2>>>(locs);                                         // 6
    cudaEventRecord(eBl, s2);
    wtrans_kernel<<<dim3(DIM / 32, INNER / 32), 256, 0, s2>>>(Wout, p_wout, INNER, DIM); // 7
    cudaEventRecord(eWout, s2);

    // main: q-GEMM (waits Wq), attn, out-GEMM
    cudaStreamWaitEvent(0, eWq, 0);
    tf32gemm_lm<128><<<dim3(INNER / 128, ROWS / 128), 128, SMEM128>>>(          // 8
        p_xn, p_wq, p_q, ROWS, INNER, DIM);

    cudaStreamWaitEvent(0, eKv, 0);
    cudaStreamWaitEvent(0, eBl, 0);
    attn_kernel<<<dim3(BATCH * HEADS * 9, NCHUNK), 256>>>();                    // 9

    cudaStreamWaitEvent(0, eWout, 0);
    tf32gemm_lm<128><<<dim3(DIM / 128, ROWS / 128), 128, SMEM128>>>(            // 10
        p_ao, p_wout, out, ROWS, DIM, INNER);
}